// round 4
// baseline (speedup 1.0000x reference)
#include <cuda_runtime.h>
#include <math.h>

// ---------------- problem constants ----------------
#define BB 1024
#define TT 128
#define FF 128
#define HH 512
#define G4 2048            // 4*HH
#define KC 768             // 2*FF + HH
#define BTn (BB*TT)        // 131072

constexpr size_t BTFc   = (size_t)BTn * FF;            // 16,777,216
constexpr size_t OFF_IMP = 0;
constexpr size_t OFF_CH1 = BTFc;
constexpr size_t OFF_HT  = 2 * BTFc;
constexpr size_t OFF_XH  = 2 * BTFc + (size_t)BB * HH;
constexpr size_t OFF_CH2 = OFF_XH + BTFc;
constexpr size_t OFF_ZH  = OFF_CH2 + BTFc;

// ---------------- device scratch (static, no allocs) ----------------
__device__ __align__(16) float g_gamma_x[(size_t)BTn * FF];   // 64 MB
__device__ __align__(16) float g_gamma_h[(size_t)BTn * HH];   // 256 MB
__device__ __align__(16) float g_alpha  [(size_t)BTn * FF];   // 64 MB
__device__ __align__(16) float g_h [BB * HH];
__device__ __align__(16) float g_c [BB * HH];
__device__ __align__(16) float g_xh[BB * FF];
__device__ __align__(16) float g_xc[BB * FF];
__device__ __align__(16) float g_cc[BB * FF];
__device__ __align__(16) float g_gates[BB * G4];
__device__ __align__(16) float g_Wod [FF * FF];
__device__ __align__(16) float g_Wcat[(size_t)G4 * KC];
__device__ __align__(16) float g_bcat[G4];

__device__ __forceinline__ float sigm(float x) { return 1.0f / (1.0f + expf(-x)); }

// ---------------- precompute: gamma_x, W_feat off-diag, W_cat, b_cat, zero state ----------------
__global__ void k_prep(const float* __restrict__ D,   const float* __restrict__ Wgx,
                       const float* __restrict__ bgx, const float* __restrict__ Wfeat,
                       const float* __restrict__ Wih, const float* __restrict__ Whh,
                       const float* __restrict__ bih, const float* __restrict__ bhh)
{
    size_t tid    = (size_t)blockIdx.x * blockDim.x + threadIdx.x;
    size_t stride = (size_t)gridDim.x * blockDim.x;

    for (size_t i = tid; i < (size_t)BTn * FF; i += stride) {
        int f = (int)(i & (FF - 1));
        float v = D[i] * Wgx[f * FF + f] + bgx[f];   // diagonal of W_gx only
        g_gamma_x[i] = expf(-fmaxf(v, 0.0f));
    }
    for (size_t i = tid; i < (size_t)G4 * KC; i += stride) {
        int n = (int)(i / KC), k = (int)(i % KC);
        g_Wcat[i] = (k < 2 * FF) ? Wih[(size_t)n * (2 * FF) + k]
                                 : Whh[(size_t)n * HH + (k - 2 * FF)];
    }
    for (size_t i = tid; i < (size_t)FF * FF; i += stride) {
        int r = (int)(i / FF), c2 = (int)(i % FF);
        g_Wod[i] = (r == c2) ? 0.0f : Wfeat[i];      // zero the diagonal
    }
    for (size_t i = tid; i < (size_t)G4; i += stride) g_bcat[i] = bih[i] + bhh[i];
    for (size_t i = tid; i < (size_t)BB * HH; i += stride) { g_h[i] = 0.0f; g_c[i] = 0.0f; }
}

// ---------------- fused tiled GEMM (64x64 tile, BK=16, 256 threads, 4x4/thread) ----------------
enum Mode { M_GH = 0, M_ALPHA = 1, M_XH = 2, M_ZH = 3, M_GATES = 4 };

template <int MODE>
__device__ __forceinline__ float4 loadA(int row, int k, int t,
    const float* __restrict__ X, const float* __restrict__ Mm, const float* __restrict__ D)
{
    if (MODE == M_GH) {
        return *(const float4*)(D + (size_t)row * FF + k);
    } else if (MODE == M_ALPHA) {
        if (k < FF) return *(const float4*)(g_gamma_x + (size_t)row * FF + k);
        return *(const float4*)(Mm + (size_t)row * FF + (k - FF));
    } else if (MODE == M_XH) {
        float4 h = *(const float4*)(g_h + (size_t)row * HH + k);
        float4 g = *(const float4*)(g_gamma_h + ((size_t)row * TT + t) * HH + k);
        return make_float4(h.x * g.x, h.y * g.y, h.z * g.z, h.w * g.w);
    } else if (MODE == M_ZH) {
        return *(const float4*)(g_xc + (size_t)row * FF + k);
    } else { // M_GATES : A row = [c_c(128) | m_t(128) | h*gamma_h(512)]
        if (k < FF)     return *(const float4*)(g_cc + (size_t)row * FF + k);
        if (k < 2 * FF) return *(const float4*)(Mm + ((size_t)row * TT + t) * FF + (k - FF));
        int kh = k - 2 * FF;
        float4 h = *(const float4*)(g_h + (size_t)row * HH + kh);
        float4 g = *(const float4*)(g_gamma_h + ((size_t)row * TT + t) * HH + kh);
        return make_float4(h.x * g.x, h.y * g.y, h.z * g.z, h.w * g.w);
    }
}

template <int MODE>
__global__ __launch_bounds__(256, 2) void k_gemm(int t,
    const float* __restrict__ X, const float* __restrict__ Mm,
    const float* __restrict__ D, const float* __restrict__ W,
    const float* __restrict__ bias, float* __restrict__ outp)
{
    constexpr int KD = (MODE == M_GH) ? FF : (MODE == M_ALPHA) ? 2 * FF
                     : (MODE == M_XH) ? HH : (MODE == M_ZH) ? FF : KC;

    __shared__ float As[16][68];
    __shared__ float Bs[16][68];

    const int tid = threadIdx.x;
    const int m0 = blockIdx.x * 64, n0 = blockIdx.y * 64;
    const int lr = tid >> 2;            // 0..63 : tile row for loading
    const int lk = (tid & 3) << 2;      // 0,4,8,12 : k quad for loading
    const int tx = tid & 15, ty = tid >> 4;

    const float* Wp = (MODE == M_ZH) ? g_Wod : (MODE == M_GATES) ? g_Wcat : W;

    float acc[4][4];
    #pragma unroll
    for (int i = 0; i < 4; i++)
        #pragma unroll
        for (int j = 0; j < 4; j++) acc[i][j] = 0.0f;

    for (int kt = 0; kt < KD; kt += 16) {
        float4 a = loadA<MODE>(m0 + lr, kt + lk, t, X, Mm, D);
        float4 b = *(const float4*)(Wp + (size_t)(n0 + lr) * KD + kt + lk);
        __syncthreads();   // previous compute done before smem overwrite
        As[lk + 0][lr] = a.x; As[lk + 1][lr] = a.y; As[lk + 2][lr] = a.z; As[lk + 3][lr] = a.w;
        Bs[lk + 0][lr] = b.x; Bs[lk + 1][lr] = b.y; Bs[lk + 2][lr] = b.z; Bs[lk + 3][lr] = b.w;
        __syncthreads();
        #pragma unroll
        for (int k = 0; k < 16; k++) {
            float4 av = *(const float4*)&As[k][ty << 2];
            float4 bv = *(const float4*)&Bs[k][tx << 2];
            float aa[4] = {av.x, av.y, av.z, av.w};
            float bb[4] = {bv.x, bv.y, bv.z, bv.w};
            #pragma unroll
            for (int i = 0; i < 4; i++)
                #pragma unroll
                for (int j = 0; j < 4; j++)
                    acc[i][j] = fmaf(aa[i], bb[j], acc[i][j]);
        }
    }

    // ---- fused epilogues ----
    #pragma unroll
    for (int i = 0; i < 4; i++) {
        const int r = m0 + (ty << 2) + i;
        #pragma unroll
        for (int j = 0; j < 4; j++) {
            const int c = n0 + (tx << 2) + j;
            float v = acc[i][j];
            if (MODE == M_GH) {
                v += bias[c];
                g_gamma_h[(size_t)r * HH + c] = expf(-fmaxf(v, 0.0f));
            } else if (MODE == M_ALPHA) {
                v += bias[c];
                g_alpha[(size_t)r * FF + c] = sigm(v);
            } else if (MODE == M_XH) {
                v += bias[c];
                size_t idx = ((size_t)r * TT + t) * FF + c;
                outp[OFF_XH + idx] = v;
                g_xh[r * FF + c] = v;
                float mm = Mm[idx], xx = X[idx];
                g_xc[r * FF + c] = mm * xx + (1.0f - mm) * v;
            } else if (MODE == M_ZH) {
                v += bias[c];
                size_t idx = ((size_t)r * TT + t) * FF + c;
                float al = g_alpha[idx];
                float xh = g_xh[r * FF + c];
                float ch = al * v + (1.0f - al) * xh;
                float mm = Mm[idx], xx = X[idx];
                float cc = mm * xx + (1.0f - mm) * ch;   // == imputed
                outp[OFF_ZH  + idx] = v;
                outp[OFF_CH1 + idx] = ch;
                outp[OFF_CH2 + idx] = ch;
                outp[OFF_IMP + idx] = cc;
                g_cc[r * FF + c] = cc;
            } else { // M_GATES
                g_gates[(size_t)r * G4 + c] = v + g_bcat[c];
            }
        }
    }
}

// ---------------- LSTM pointwise update ----------------
__global__ void k_lstm()
{
    int i = blockIdx.x * blockDim.x + threadIdx.x;
    if (i >= BB * HH) return;
    int b = i >> 9, j = i & (HH - 1);
    const float* gr = g_gates + (size_t)b * G4;
    float ig = sigm(gr[j]);
    float fg = sigm(gr[HH + j]);
    float gg = tanhf(gr[2 * HH + j]);
    float og = sigm(gr[3 * HH + j]);
    float c = fg * g_c[i] + ig * gg;
    g_c[i] = c;
    g_h[i] = og * tanhf(c);
}

__global__ void k_hT(float* __restrict__ outp)
{
    int i = blockIdx.x * blockDim.x + threadIdx.x;
    if (i < BB * HH) outp[OFF_HT + i] = g_h[i];
}

// ---------------- launch ----------------
extern "C" void kernel_launch(void* const* d_in, const int* in_sizes, int n_in,
                              void* d_out, int out_size)
{
    const float* X      = (const float*)d_in[0];
    const float* Mm     = (const float*)d_in[1];
    const float* D      = (const float*)d_in[2];
    const float* W_gh   = (const float*)d_in[3];
    const float* b_gh   = (const float*)d_in[4];
    const float* W_gx   = (const float*)d_in[5];
    const float* b_gx   = (const float*)d_in[6];
    const float* W_hist = (const float*)d_in[7];
    const float* b_hist = (const float*)d_in[8];
    const float* W_feat = (const float*)d_in[9];
    const float* b_feat = (const float*)d_in[10];
    const float* W_comb = (const float*)d_in[11];
    const float* b_comb = (const float*)d_in[12];
    const float* W_ih   = (const float*)d_in[13];
    const float* W_hh   = (const float*)d_in[14];
    const float* b_ih   = (const float*)d_in[15];
    const float* b_hh   = (const float*)d_in[16];
    float* outp = (float*)d_out;

    // Parallel precompute: everything that does not depend on the carry.
    k_prep<<<4096, 256>>>(D, W_gx, b_gx, W_feat, W_ih, W_hh, b_ih, b_hh);
    k_gemm<M_GH>   <<<dim3(BTn / 64, HH / 64), 256>>>(0, X, Mm, D, W_gh,   b_gh,   outp);
    k_gemm<M_ALPHA><<<dim3(BTn / 64, FF / 64), 256>>>(0, X, Mm, D, W_comb, b_comb, outp);

    // Serial scan: 4 launches per step.
    for (int t = 0; t < TT; t++) {
        k_gemm<M_XH>   <<<dim3(BB / 64, FF / 64), 256>>>(t, X, Mm, D, W_hist, b_hist, outp);
        k_gemm<M_ZH>   <<<dim3(BB / 64, FF / 64), 256>>>(t, X, Mm, D, nullptr, b_feat, outp);
        k_gemm<M_GATES><<<dim3(BB / 64, G4 / 64), 256>>>(t, X, Mm, D, nullptr, nullptr, outp);
        k_lstm<<<(BB * HH) / 256, 256>>>();
    }
    k_hT<<<(BB * HH) / 256, 256>>>(outp);
}

// round 5
// speedup vs baseline: 2.2967x; 2.2967x over previous
#include <cuda_runtime.h>
#include <cuda_bf16.h>
#include <math.h>
#include <stdint.h>

// ---------------- problem constants ----------------
#define BB 1024
#define TT 128
#define FF 128
#define HH 512
#define G4 2048            // 4*HH
#define KC 768             // 2*FF + HH
#define BTn (BB*TT)        // 131072

constexpr size_t BTFc   = (size_t)BTn * FF;
constexpr size_t OFF_IMP = 0;
constexpr size_t OFF_CH1 = BTFc;
constexpr size_t OFF_HT  = 2 * BTFc;
constexpr size_t OFF_XH  = 2 * BTFc + (size_t)BB * HH;
constexpr size_t OFF_CH2 = OFF_XH + BTFc;
constexpr size_t OFF_ZH  = OFF_CH2 + BTFc;

// ---------------- device scratch (static, no allocs) ----------------
__device__ __align__(16) float g_gamma_x[(size_t)BTn * FF];   // 64 MB
__device__ __align__(16) float g_gamma_h[(size_t)BTn * HH];   // 256 MB
__device__ __align__(16) float g_alpha  [(size_t)BTn * FF];   // 64 MB
__device__ __align__(16) float g_h [BB * HH];
__device__ __align__(16) float g_c [BB * HH];
__device__ __align__(16) float g_xh[BB * FF];
__device__ __align__(16) float g_xc[BB * FF];
__device__ __align__(16) float g_cc[BB * FF];
__device__ __align__(16) float g_gates[BB * G4];
__device__ __align__(16) float g_bcat[G4];

// bf16 split, TRANSPOSED weights: layout [K][N] row-major
__device__ __align__(16) __nv_bfloat16 g_WghH [FF * HH],  g_WghL [FF * HH];   // K=128, N=512
__device__ __align__(16) __nv_bfloat16 g_WcombH[256 * FF], g_WcombL[256 * FF]; // K=256, N=128
__device__ __align__(16) __nv_bfloat16 g_WhistH[HH * FF],  g_WhistL[HH * FF];  // K=512, N=128
__device__ __align__(16) __nv_bfloat16 g_WodH [FF * FF],  g_WodL [FF * FF];   // K=128, N=128
__device__ __align__(16) __nv_bfloat16 g_WcatH[(size_t)KC * G4], g_WcatL[(size_t)KC * G4]; // K=768, N=2048

__device__ __forceinline__ float sigm(float x) { return 1.0f / (1.0f + expf(-x)); }

__device__ __forceinline__ void split_w(__nv_bfloat16* H, __nv_bfloat16* L, size_t i, float w) {
    __nv_bfloat16 h = __float2bfloat16(w);
    H[i] = h;
    L[i] = __float2bfloat16(w - __bfloat162float(h));
}

// ---------------- precompute ----------------
__global__ void k_prep(const float* __restrict__ D,    const float* __restrict__ Wgx,
                       const float* __restrict__ bgx,  const float* __restrict__ Wfeat,
                       const float* __restrict__ Wih,  const float* __restrict__ Whh,
                       const float* __restrict__ bih,  const float* __restrict__ bhh,
                       const float* __restrict__ Wgh,  const float* __restrict__ Wcomb,
                       const float* __restrict__ Whist)
{
    size_t tid    = (size_t)blockIdx.x * blockDim.x + threadIdx.x;
    size_t stride = (size_t)gridDim.x * blockDim.x;

    for (size_t i = tid; i < (size_t)BTn * FF; i += stride) {
        int f = (int)(i & (FF - 1));
        float v = D[i] * Wgx[f * FF + f] + bgx[f];
        g_gamma_x[i] = expf(-fmaxf(v, 0.0f));
    }
    for (size_t i = tid; i < (size_t)G4; i += stride) g_bcat[i] = bih[i] + bhh[i];
    for (size_t i = tid; i < (size_t)BB * HH; i += stride) { g_h[i] = 0.0f; g_c[i] = 0.0f; }

    // W_gh (H=512, F=128): used as d@W^T -> N=512, K=128. Wt[k][n] = W[n][k]
    for (size_t i = tid; i < (size_t)FF * HH; i += stride) {
        int k = (int)(i / HH), n = (int)(i % HH);
        split_w(g_WghH, g_WghL, i, Wgh[(size_t)n * FF + k]);
    }
    // W_comb (F=128, 2F=256): N=128, K=256
    for (size_t i = tid; i < (size_t)256 * FF; i += stride) {
        int k = (int)(i / FF), n = (int)(i % FF);
        split_w(g_WcombH, g_WcombL, i, Wcomb[(size_t)n * 256 + k]);
    }
    // W_hist (F=128, H=512): N=128, K=512
    for (size_t i = tid; i < (size_t)HH * FF; i += stride) {
        int k = (int)(i / FF), n = (int)(i % FF);
        split_w(g_WhistH, g_WhistL, i, Whist[(size_t)n * HH + k]);
    }
    // W_feat off-diag (F,F): N=128, K=128
    for (size_t i = tid; i < (size_t)FF * FF; i += stride) {
        int k = (int)(i / FF), n = (int)(i % FF);
        float w = (k == n) ? 0.0f : Wfeat[(size_t)n * FF + k];
        split_w(g_WodH, g_WodL, i, w);
    }
    // W_cat: N=2048, K=768 ([Wih | Whh])
    for (size_t i = tid; i < (size_t)KC * G4; i += stride) {
        int k = (int)(i / G4), n = (int)(i % G4);
        float w = (k < 2 * FF) ? Wih[(size_t)n * (2 * FF) + k]
                               : Whh[(size_t)n * HH + (k - 2 * FF)];
        split_w(g_WcatH, g_WcatL, i, w);
    }
}

// ---------------- A-operand loader (fp32) ----------------
enum Mode { M_GH = 0, M_ALPHA = 1, M_XH = 2, M_ZH = 3, M_GATES = 4 };

template <int MODE>
__device__ __forceinline__ float4 loadA(int row, int k, int t,
    const float* __restrict__ X, const float* __restrict__ Mm, const float* __restrict__ D)
{
    if (MODE == M_GH) {
        return *(const float4*)(D + (size_t)row * FF + k);
    } else if (MODE == M_ALPHA) {
        if (k < FF) return *(const float4*)(g_gamma_x + (size_t)row * FF + k);
        return *(const float4*)(Mm + (size_t)row * FF + (k - FF));
    } else if (MODE == M_XH) {
        float4 h = *(const float4*)(g_h + (size_t)row * HH + k);
        float4 g = *(const float4*)(g_gamma_h + ((size_t)row * TT + t) * HH + k);
        return make_float4(h.x * g.x, h.y * g.y, h.z * g.z, h.w * g.w);
    } else if (MODE == M_ZH) {
        return *(const float4*)(g_xc + (size_t)row * FF + k);
    } else { // M_GATES : [c_c(128) | m_t(128) | h*gamma_h(512)]
        if (k < FF)     return *(const float4*)(g_cc + (size_t)row * FF + k);
        if (k < 2 * FF) return *(const float4*)(Mm + ((size_t)row * TT + t) * FF + (k - FF));
        int kh = k - 2 * FF;
        float4 h = *(const float4*)(g_h + (size_t)row * HH + kh);
        float4 g = *(const float4*)(g_gamma_h + ((size_t)row * TT + t) * HH + kh);
        return make_float4(h.x * g.x, h.y * g.y, h.z * g.z, h.w * g.w);
    }
}

// ---------------- mma helpers ----------------
__device__ __forceinline__ void ldmA(uint32_t* r, const __nv_bfloat16* p) {
    uint32_t a = (uint32_t)__cvta_generic_to_shared(p);
    asm volatile("ldmatrix.sync.aligned.m8n8.x4.shared.b16 {%0,%1,%2,%3}, [%4];"
                 : "=r"(r[0]), "=r"(r[1]), "=r"(r[2]), "=r"(r[3]) : "r"(a));
}
__device__ __forceinline__ void ldmBT(uint32_t* r, const __nv_bfloat16* p) {
    uint32_t a = (uint32_t)__cvta_generic_to_shared(p);
    asm volatile("ldmatrix.sync.aligned.m8n8.x4.trans.shared.b16 {%0,%1,%2,%3}, [%4];"
                 : "=r"(r[0]), "=r"(r[1]), "=r"(r[2]), "=r"(r[3]) : "r"(a));
}
__device__ __forceinline__ void mma16816(float* d, const uint32_t* a, const uint32_t* b) {
    asm volatile("mma.sync.aligned.m16n8k16.row.col.f32.bf16.bf16.f32 "
                 "{%0,%1,%2,%3}, {%4,%5,%6,%7}, {%8,%9}, {%0,%1,%2,%3};"
                 : "+f"(d[0]), "+f"(d[1]), "+f"(d[2]), "+f"(d[3])
                 : "r"(a[0]), "r"(a[1]), "r"(a[2]), "r"(a[3]), "r"(b[0]), "r"(b[1]));
}

__device__ __forceinline__ void splitA_store(__nv_bfloat16* pH, __nv_bfloat16* pL, float4 a) {
    __nv_bfloat16 h0 = __float2bfloat16(a.x), h1 = __float2bfloat16(a.y);
    __nv_bfloat16 h2 = __float2bfloat16(a.z), h3 = __float2bfloat16(a.w);
    __nv_bfloat16 l0 = __float2bfloat16(a.x - __bfloat162float(h0));
    __nv_bfloat16 l1 = __float2bfloat16(a.y - __bfloat162float(h1));
    __nv_bfloat16 l2 = __float2bfloat16(a.z - __bfloat162float(h2));
    __nv_bfloat16 l3 = __float2bfloat16(a.w - __bfloat162float(h3));
    ((__nv_bfloat162*)pH)[0] = __halves2bfloat162(h0, h1);
    ((__nv_bfloat162*)pH)[1] = __halves2bfloat162(h2, h3);
    ((__nv_bfloat162*)pL)[0] = __halves2bfloat162(l0, l1);
    ((__nv_bfloat162*)pL)[1] = __halves2bfloat162(l2, l3);
}

// ---------------- bf16x3 split-precision tensor-core GEMM ----------------
template <int MODE, int BM, int BN, int WARPS_M, int WARPS_N>
__global__ __launch_bounds__(WARPS_M * WARPS_N * 32)
void k_mma(int t, const float* __restrict__ X, const float* __restrict__ Mm,
           const float* __restrict__ D, const float* __restrict__ bias,
           float* __restrict__ outp)
{
    constexpr int KD = (MODE == M_GH) ? FF : (MODE == M_ALPHA) ? 2 * FF
                     : (MODE == M_XH) ? HH : (MODE == M_ZH) ? FF : KC;
    constexpr int ND = (MODE == M_GH) ? HH : (MODE == M_GATES) ? G4 : FF;
    constexpr int NT    = WARPS_M * WARPS_N * 32;
    constexpr int WTN   = BN / WARPS_N;          // warp n-tile (16 or 32)
    constexpr int NFRAG = WTN / 8;               // 2 or 4
    constexpr int LDA   = 40;                    // 32 + 8 pad (bf16 elems)
    constexpr int LDB   = BN + 8;
    constexpr int CH    = (32 * BN / 8) / NT;    // uint4 chunks per thread (== 2)

    const __nv_bfloat16* WH = (MODE == M_GH) ? g_WghH : (MODE == M_ALPHA) ? g_WcombH
                            : (MODE == M_XH) ? g_WhistH : (MODE == M_ZH) ? g_WodH : g_WcatH;
    const __nv_bfloat16* WL = (MODE == M_GH) ? g_WghL : (MODE == M_ALPHA) ? g_WcombL
                            : (MODE == M_XH) ? g_WhistL : (MODE == M_ZH) ? g_WodL : g_WcatL;

    __shared__ __align__(16) __nv_bfloat16 AsH[BM * LDA], AsL[BM * LDA];
    __shared__ __align__(16) __nv_bfloat16 BsH[32 * LDB], BsL[32 * LDB];

    const int tid  = threadIdx.x;
    const int lane = tid & 31;
    const int w    = tid >> 5;
    const int wm   = w / WARPS_N, wn = w % WARPS_N;
    const int m0   = blockIdx.x * BM, n0 = blockIdx.y * BN;
    const int mA   = tid >> 2;              // A-load row within tile
    const int kA   = (tid & 3) * 4;         // A-load k quad (0,4,8,12)
    const int lr   = lane & 15;             // ldmatrix row
    const int lc   = (lane >> 4) * 8;       // ldmatrix col half

    float acc[2][NFRAG][4];
    #pragma unroll
    for (int i = 0; i < 2; i++)
        #pragma unroll
        for (int nb = 0; nb < NFRAG; nb++)
            #pragma unroll
            for (int e = 0; e < 4; e++) acc[i][nb][e] = 0.0f;

    for (int kt = 0; kt < KD; kt += 32) {
        float4 a1 = loadA<MODE>(m0 + mA, kt + kA,      t, X, Mm, D);
        float4 a2 = loadA<MODE>(m0 + mA, kt + kA + 16, t, X, Mm, D);
        uint4 bqh[CH], bql[CH];
        #pragma unroll
        for (int q = 0; q < CH; q++) {
            int cidx = q * NT + tid;
            int row = cidx / (BN / 8), col = (cidx % (BN / 8)) * 8;
            size_t gi = (size_t)(kt + row) * ND + n0 + col;
            bqh[q] = *(const uint4*)(WH + gi);
            bql[q] = *(const uint4*)(WL + gi);
        }
        __syncthreads();
        splitA_store(&AsH[mA * LDA + kA],      &AsL[mA * LDA + kA],      a1);
        splitA_store(&AsH[mA * LDA + kA + 16], &AsL[mA * LDA + kA + 16], a2);
        #pragma unroll
        for (int q = 0; q < CH; q++) {
            int cidx = q * NT + tid;
            int row = cidx / (BN / 8), col = (cidx % (BN / 8)) * 8;
            *(uint4*)&BsH[row * LDB + col] = bqh[q];
            *(uint4*)&BsL[row * LDB + col] = bql[q];
        }
        __syncthreads();
        #pragma unroll
        for (int kk = 0; kk < 32; kk += 16) {
            uint32_t ah[2][4], al[2][4];
            #pragma unroll
            for (int i = 0; i < 2; i++) {
                const int rowb = wm * 32 + i * 16 + lr;
                ldmA(ah[i], &AsH[rowb * LDA + kk + lc]);
                ldmA(al[i], &AsL[rowb * LDA + kk + lc]);
            }
            uint32_t bh[NFRAG][2], bl[NFRAG][2];
            #pragma unroll
            for (int g = 0; g < NFRAG / 2; g++) {
                uint32_t r4[4];
                const int coff = wn * WTN + g * 16 + lc;
                ldmBT(r4, &BsH[(kk + lr) * LDB + coff]);
                bh[2*g][0] = r4[0]; bh[2*g][1] = r4[1];
                bh[2*g+1][0] = r4[2]; bh[2*g+1][1] = r4[3];
                ldmBT(r4, &BsL[(kk + lr) * LDB + coff]);
                bl[2*g][0] = r4[0]; bl[2*g][1] = r4[1];
                bl[2*g+1][0] = r4[2]; bl[2*g+1][1] = r4[3];
            }
            #pragma unroll
            for (int i = 0; i < 2; i++)
                #pragma unroll
                for (int nb = 0; nb < NFRAG; nb++) {
                    mma16816(acc[i][nb], ah[i], bh[nb]);   // hi*hi
                    mma16816(acc[i][nb], al[i], bh[nb]);   // lo*hi
                    mma16816(acc[i][nb], ah[i], bl[nb]);   // hi*lo
                }
        }
    }

    // ---- fused epilogues (fragment layout: d0,d1=(r,c/c+1), d2,d3=(r+8,·)) ----
    #pragma unroll
    for (int i = 0; i < 2; i++) {
        #pragma unroll
        for (int nb = 0; nb < NFRAG; nb++) {
            const int rbase = m0 + wm * 32 + i * 16 + (lane >> 2);
            const int cbase = n0 + wn * WTN + nb * 8 + (lane & 3) * 2;
            #pragma unroll
            for (int e = 0; e < 4; e++) {
                const int r = rbase + (e >> 1) * 8;
                const int c = cbase + (e & 1);
                float v = acc[i][nb][e];
                if (MODE == M_GH) {
                    v += bias[c];
                    g_gamma_h[(size_t)r * HH + c] = expf(-fmaxf(v, 0.0f));
                } else if (MODE == M_ALPHA) {
                    v += bias[c];
                    g_alpha[(size_t)r * FF + c] = sigm(v);
                } else if (MODE == M_XH) {
                    v += bias[c];
                    size_t idx = ((size_t)r * TT + t) * FF + c;
                    outp[OFF_XH + idx] = v;
                    g_xh[r * FF + c] = v;
                    float mm = Mm[idx], xx = X[idx];
                    g_xc[r * FF + c] = mm * xx + (1.0f - mm) * v;
                } else if (MODE == M_ZH) {
                    v += bias[c];
                    size_t idx = ((size_t)r * TT + t) * FF + c;
                    float al2 = g_alpha[idx];
                    float xh  = g_xh[r * FF + c];
                    float ch  = al2 * v + (1.0f - al2) * xh;
                    float mm  = Mm[idx], xx = X[idx];
                    float cc  = mm * xx + (1.0f - mm) * ch;
                    outp[OFF_ZH  + idx] = v;
                    outp[OFF_CH1 + idx] = ch;
                    outp[OFF_CH2 + idx] = ch;
                    outp[OFF_IMP + idx] = cc;
                    g_cc[r * FF + c] = cc;
                } else { // M_GATES
                    g_gates[(size_t)r * G4 + c] = v + g_bcat[c];
                }
            }
        }
    }
}

// ---------------- LSTM pointwise update ----------------
__global__ void k_lstm()
{
    int i = blockIdx.x * blockDim.x + threadIdx.x;
    if (i >= BB * HH) return;
    int b = i >> 9, j = i & (HH - 1);
    const float* gr = g_gates + (size_t)b * G4;
    float ig = sigm(gr[j]);
    float fg = sigm(gr[HH + j]);
    float gg = tanhf(gr[2 * HH + j]);
    float og = sigm(gr[3 * HH + j]);
    float c = fg * g_c[i] + ig * gg;
    g_c[i] = c;
    g_h[i] = og * tanhf(c);
}

__global__ void k_hT(float* __restrict__ outp)
{
    int i = blockIdx.x * blockDim.x + threadIdx.x;
    if (i < BB * HH) outp[OFF_HT + i] = g_h[i];
}

// ---------------- launch ----------------
extern "C" void kernel_launch(void* const* d_in, const int* in_sizes, int n_in,
                              void* d_out, int out_size)
{
    const float* X      = (const float*)d_in[0];
    const float* Mm     = (const float*)d_in[1];
    const float* D      = (const float*)d_in[2];
    const float* W_gh   = (const float*)d_in[3];
    const float* b_gh   = (const float*)d_in[4];
    const float* W_gx   = (const float*)d_in[5];
    const float* b_gx   = (const float*)d_in[6];
    const float* W_hist = (const float*)d_in[7];
    const float* b_hist = (const float*)d_in[8];
    const float* W_feat = (const float*)d_in[9];
    const float* b_feat = (const float*)d_in[10];
    const float* W_comb = (const float*)d_in[11];
    const float* b_comb = (const float*)d_in[12];
    const float* W_ih   = (const float*)d_in[13];
    const float* W_hh   = (const float*)d_in[14];
    const float* b_ih   = (const float*)d_in[15];
    const float* b_hh   = (const float*)d_in[16];
    float* outp = (float*)d_out;

    // Parallel precompute (carry-independent)
    k_prep<<<4096, 256>>>(D, W_gx, b_gx, W_feat, W_ih, W_hh, b_ih, b_hh,
                          W_gh, W_comb, W_hist);
    k_mma<M_GH,    64, 128, 2, 4><<<dim3(BTn / 64, HH / 128), 256>>>(0, X, Mm, D, b_gh,   outp);
    k_mma<M_ALPHA, 64, 128, 2, 4><<<dim3(BTn / 64, 1),        256>>>(0, X, Mm, D, b_comb, outp);

    // Serial scan: 4 launches per step
    for (int t = 0; t < TT; t++) {
        k_mma<M_XH,    32, 64, 1, 4><<<dim3(BB / 32, FF / 64), 128>>>(t, X, Mm, D, b_hist, outp);
        k_mma<M_ZH,    32, 64, 1, 4><<<dim3(BB / 32, FF / 64), 128>>>(t, X, Mm, D, b_feat, outp);
        k_mma<M_GATES, 64, 128, 2, 4><<<dim3(BB / 64, G4 / 128), 256>>>(t, X, Mm, D, nullptr, outp);
        k_lstm<<<(BB * HH) / 256, 256>>>();
    }
    k_hT<<<(BB * HH) / 256, 256>>>(outp);
}